// round 3
// baseline (speedup 1.0000x reference)
#include <cuda_runtime.h>
#include <math.h>

// Problem constants
#define BB 4
#define NN 16384
#define MM 512
#define COLS1 131072   // BB*MM*64  (ball branch columns)
#define COLS2 18432    // BB*MM*9   (knn branch columns)
#define COLSN 2048     // BB*MM

// ---------------- static scratch (no allocations allowed) ----------------
__device__ float d_bufA[128 * 131072];   // 64 MiB ping
__device__ float d_bufB[128 * 131072];   // 64 MiB pong
__device__ float d_X0[6 * 131072];       // gathered ball input (6 x COLS1)
__device__ float d_H[640 * 2048];        // rows 0..127 = feat1, 128..639 = feat2
__device__ int   d_ballidx[131072];      // (B*M, 64)
__device__ int   d_knnidx[18432];        // (B*M, 9)

// ---------------- generic tiled SGEMM: C = [relu](W @ X + bias) ----------
// W: [Mrows x K] row-major, X: [K x Ncols] row-major, C: [Mrows x Ncols]
// block tile 64(rows) x 128(cols), BK=16, 256 threads, 4x8 per-thread tile.
#define GBM 64
#define GBN 128
#define GBK 16
__global__ void __launch_bounds__(256, 2)
gemm_bias_relu(const float* __restrict__ W, const float* __restrict__ X,
               const float* __restrict__ bias, float* __restrict__ C,
               int Mrows, int K, int Ncols, int do_relu)
{
    __shared__ float Ws[GBK][GBM + 4];   // [kk][co], padded
    __shared__ float Xs[GBK][GBN];       // [kk][col]

    int tid = threadIdx.x;
    int ty = tid >> 4;          // 0..15
    int tx = tid & 15;          // 0..15
    int co0  = blockIdx.y * GBM;
    int col0 = blockIdx.x * GBN;

    float acc[4][8];
#pragma unroll
    for (int i = 0; i < 4; i++)
#pragma unroll
        for (int j = 0; j < 8; j++) acc[i][j] = 0.f;

    for (int k0 = 0; k0 < K; k0 += GBK) {
        // load W tile (64x16), 4 scalars per thread, zero-pad beyond K
        {
            int kk = tid & 15;
            int r  = tid >> 4;
            int kg = k0 + kk;
#pragma unroll
            for (int j = 0; j < 4; j++) {
                int co = r + j * 16;
                float v = 0.f;
                if (kg < K) v = W[(size_t)(co0 + co) * K + kg];
                Ws[kk][co] = v;
            }
        }
        // load X tile (16x128) as float4, 2 per thread, zero-pad beyond K
        {
            int cl  = (tid & 31) << 2;   // 0..124 step 4
            int kk0 = tid >> 5;          // 0..7
#pragma unroll
            for (int j = 0; j < 2; j++) {
                int kk = kk0 + 8 * j;
                int kg = k0 + kk;
                float4 v = make_float4(0.f, 0.f, 0.f, 0.f);
                if (kg < K)
                    v = *reinterpret_cast<const float4*>(&X[(size_t)kg * Ncols + col0 + cl]);
                *reinterpret_cast<float4*>(&Xs[kk][cl]) = v;
            }
        }
        __syncthreads();

#pragma unroll
        for (int kk = 0; kk < GBK; kk++) {
            float4 a4  = *reinterpret_cast<const float4*>(&Ws[kk][ty * 4]);
            float4 b4a = *reinterpret_cast<const float4*>(&Xs[kk][tx * 8]);
            float4 b4b = *reinterpret_cast<const float4*>(&Xs[kk][tx * 8 + 4]);
            float a[4] = {a4.x, a4.y, a4.z, a4.w};
            float b[8] = {b4a.x, b4a.y, b4a.z, b4a.w, b4b.x, b4b.y, b4b.z, b4b.w};
#pragma unroll
            for (int i = 0; i < 4; i++)
#pragma unroll
                for (int j = 0; j < 8; j++)
                    acc[i][j] += a[i] * b[j];
        }
        __syncthreads();
    }

    // epilogue: bias + relu, vectorized stores
#pragma unroll
    for (int i = 0; i < 4; i++) {
        int co = co0 + ty * 4 + i;
        float bs = bias[co];
        float out[8];
#pragma unroll
        for (int j = 0; j < 8; j++) {
            float v = acc[i][j] + bs;
            if (do_relu) v = fmaxf(v, 0.f);
            out[j] = v;
        }
        float* dst = &C[(size_t)co * Ncols + col0 + tx * 8];
        *reinterpret_cast<float4*>(dst)     = make_float4(out[0], out[1], out[2], out[3]);
        *reinterpret_cast<float4*>(dst + 4) = make_float4(out[4], out[5], out[6], out[7]);
    }
}

// ---------------- ball query: first 64 in-ball indices in index order -----
__global__ void ball_query_kernel(const float* __restrict__ x,
                                  const float* __restrict__ node,
                                  int* __restrict__ idxout)
{
    int w = (blockIdx.x * blockDim.x + threadIdx.x) >> 5;
    int lane = threadIdx.x & 31;
    if (w >= BB * MM) return;
    int b = w / MM, m = w % MM;
    float nx = node[(b * 3 + 0) * MM + m];
    float ny = node[(b * 3 + 1) * MM + m];
    float nz = node[(b * 3 + 2) * MM + m];
    const float* xb = x + (size_t)b * 3 * NN;
    int base = w * 64;
    int total = 0;
    int firstJ = -1;
    for (int j0 = 0; j0 < NN; j0 += 32) {
        int j = j0 + lane;
        float dx = xb[j] - nx;
        float dy = xb[NN + j] - ny;
        float dz = xb[2 * NN + j] - nz;
        float d = dx * dx + dy * dy + dz * dz;
        bool hit = d < 4.0f;
        unsigned mask = __ballot_sync(0xffffffffu, hit);
        if (firstJ < 0 && mask) firstJ = j0 + __ffs(mask) - 1;
        int pos = total + __popc(mask & ((1u << lane) - 1u));
        if (hit && pos < 64) idxout[base + pos] = j;
        total += __popc(mask);
        if (total >= 64) break;
    }
    if (total < 64) {
        int f = (firstJ < 0) ? 0 : firstJ;
        for (int p = total + lane; p < 64; p += 32) idxout[base + p] = f;
    }
}

// ---------------- gather ball neighborhood: X0 (6 x COLS1) ---------------
__global__ void gather_xb_kernel(const float* __restrict__ x,
                                 const float* __restrict__ sn,
                                 const float* __restrict__ node,
                                 const int* __restrict__ idx,
                                 float* __restrict__ X0)
{
    int col = blockIdx.x * blockDim.x + threadIdx.x;
    if (col >= COLS1) return;
    int nodeid = col >> 6;          // b*MM + m
    int b = nodeid / MM, m = nodeid % MM;
    int j = idx[col];
    const float* xb = x  + (size_t)b * 3 * NN;
    const float* sb = sn + (size_t)b * 3 * NN;
    X0[(size_t)0 * COLS1 + col] = xb[j]          - node[(b * 3 + 0) * MM + m];
    X0[(size_t)1 * COLS1 + col] = xb[NN + j]     - node[(b * 3 + 1) * MM + m];
    X0[(size_t)2 * COLS1 + col] = xb[2 * NN + j] - node[(b * 3 + 2) * MM + m];
    X0[(size_t)3 * COLS1 + col] = sb[j];
    X0[(size_t)4 * COLS1 + col] = sb[NN + j];
    X0[(size_t)5 * COLS1 + col] = sb[2 * NN + j];
}

// -------- max over k=64 and concat: in (64 x COLS1) -> out (128 x COLS1) --
__global__ void max64_concat_kernel(const float* __restrict__ f,
                                    float* __restrict__ g)
{
    int nodeid = blockIdx.x;        // 0..2047
    int row = blockIdx.y;           // 0..63
    int k = threadIdx.x;            // 0..63
    size_t off = (size_t)row * COLS1 + nodeid * 64 + k;
    float v = f[off];
    float mv = v;
#pragma unroll
    for (int o = 16; o; o >>= 1) mv = fmaxf(mv, __shfl_xor_sync(0xffffffffu, mv, o));
    __shared__ float s[2];
    if ((k & 31) == 0) s[k >> 5] = mv;
    __syncthreads();
    float mx = fmaxf(s[0], s[1]);
    g[off] = v;
    g[(size_t)(row + 64) * COLS1 + nodeid * 64 + k] = mx;
}

// -------- final max over k=64 -> feat1 rows of H:  H[c][b*MM+m] -----------
__global__ void max64_final_kernel(const float* __restrict__ f,
                                   float* __restrict__ Hrows)
{
    int nodeid = blockIdx.x;        // 0..2047
    int row = blockIdx.y;           // 0..127
    int k = threadIdx.x;            // 0..63
    float v = f[(size_t)row * COLS1 + nodeid * 64 + k];
#pragma unroll
    for (int o = 16; o; o >>= 1) v = fmaxf(v, __shfl_xor_sync(0xffffffffu, v, o));
    __shared__ float s[2];
    if ((k & 31) == 0) s[k >> 5] = v;
    __syncthreads();
    if (k == 0) Hrows[(size_t)row * COLSN + nodeid] = fmaxf(s[0], s[1]);
}

// ---------------- 9-NN among nodes (tie-break: smaller index) -------------
__global__ void knn_select_kernel(const float* __restrict__ node,
                                  int* __restrict__ knnidx)
{
    int nid = blockIdx.x;           // 0..2047
    int b = nid >> 9, m = nid & 511;
    int j = threadIdx.x;            // 0..511
    __shared__ float rd[16];
    __shared__ int   ri[16];
    __shared__ int   sbest;
    float nx = node[(b * 3 + 0) * MM + m];
    float ny = node[(b * 3 + 1) * MM + m];
    float nz = node[(b * 3 + 2) * MM + m];
    float dx = node[(b * 3 + 0) * MM + j] - nx;
    float dy = node[(b * 3 + 1) * MM + j] - ny;
    float dz = node[(b * 3 + 2) * MM + j] - nz;
    float d = dx * dx + dy * dy + dz * dz;
    for (int t = 0; t < 9; t++) {
        float bd = d; int bi = j;
#pragma unroll
        for (int o = 16; o; o >>= 1) {
            float od = __shfl_xor_sync(0xffffffffu, bd, o);
            int   oi = __shfl_xor_sync(0xffffffffu, bi, o);
            if (od < bd || (od == bd && oi < bi)) { bd = od; bi = oi; }
        }
        if ((j & 31) == 0) { rd[j >> 5] = bd; ri[j >> 5] = bi; }
        __syncthreads();
        if (j == 0) {
            float best = rd[0]; int besti = ri[0];
            for (int w = 1; w < 16; w++)
                if (rd[w] < best || (rd[w] == best && ri[w] < besti)) { best = rd[w]; besti = ri[w]; }
            knnidx[nid * 9 + t] = besti;
            sbest = besti;
        }
        __syncthreads();
        if (j == sbest) d = 3.4e38f;
    }
}

// -------- gather knn inputs: g0 (131 x COLS2): [coords-diff(3); feat1(128)]
__global__ void gather_knn_kernel(const float* __restrict__ node,
                                  const float* __restrict__ H,   // feat1 rows 0..127
                                  const int* __restrict__ knnidx,
                                  float* __restrict__ g0)
{
    int e = blockIdx.x * blockDim.x + threadIdx.x;
    if (e >= 131 * COLS2) return;
    int row = e / COLS2, col = e % COLS2;
    int nid = col / 9;
    int b = nid >> 9, m = nid & 511;
    int j = knnidx[col];
    float v;
    if (row < 3)
        v = node[(b * 3 + row) * MM + j] - node[(b * 3 + row) * MM + m];
    else
        v = H[(size_t)(row - 3) * COLSN + b * MM + j];
    g0[e] = v;
}

// -------- max over k=9 and concat: in (256 x COLS2) -> out (512 x COLS2) --
__global__ void max9_concat_kernel(const float* __restrict__ g,
                                   float* __restrict__ o)
{
    int e = blockIdx.x * blockDim.x + threadIdx.x;
    if (e >= 256 * COLSN) return;
    int row = e / COLSN, nid = e % COLSN;
    size_t base = (size_t)row * COLS2 + nid * 9;
    float mx = -3.4e38f;
    float vals[9];
#pragma unroll
    for (int k = 0; k < 9; k++) { vals[k] = g[base + k]; mx = fmaxf(mx, vals[k]); }
#pragma unroll
    for (int k = 0; k < 9; k++) {
        o[base + k] = vals[k];
        o[(size_t)(row + 256) * COLS2 + nid * 9 + k] = mx;
    }
}

// -------- final max over k=9 -> feat2 rows 128..639 of H ------------------
__global__ void max9_final_kernel(const float* __restrict__ g,
                                  float* __restrict__ Hrows)   // points at H+128*COLSN
{
    int e = blockIdx.x * blockDim.x + threadIdx.x;
    if (e >= 512 * COLSN) return;
    int row = e / COLSN, nid = e % COLSN;
    size_t base = (size_t)row * COLS2 + nid * 9;
    float mx = -3.4e38f;
#pragma unroll
    for (int k = 0; k < 9; k++) mx = fmaxf(mx, g[base + k]);
    Hrows[(size_t)row * COLSN + nid] = mx;
}

// -------- head: mlp3 (4x256) + softplus + assemble final output ----------
__global__ void head_kernel(const float* __restrict__ m2,    // 256 x 2048
                            const float* __restrict__ w3,    // 4 x 256
                            const float* __restrict__ b3,    // 4
                            const float* __restrict__ node,
                            float* __restrict__ out)
{
    int col = blockIdx.x * blockDim.x + threadIdx.x;
    if (col >= COLSN) return;
    int b = col >> 9, m = col & 511;
    float acc0 = b3[0], acc1 = b3[1], acc2 = b3[2], acc3 = b3[3];
    for (int ci = 0; ci < 256; ci++) {
        float xv = m2[(size_t)ci * COLSN + col];
        acc0 += w3[0 * 256 + ci] * xv;
        acc1 += w3[1 * 256 + ci] * xv;
        acc2 += w3[2 * 256 + ci] * xv;
        acc3 += w3[3 * 256 + ci] * xv;
    }
    float kv[3] = {acc0, acc1, acc2};
#pragma unroll
    for (int c = 0; c < 3; c++) {
        float nv = node[(b * 3 + c) * MM + m];
        out[(b * 3 + c) * MM + m] = nv;                   // node passthrough
        out[6144 + (b * 3 + c) * MM + m] = kv[c] + nv;    // keypoints
    }
    // softplus(acc3) + 0.001 (numerically stable form matching jax)
    float s = acc3;
    float sp = fmaxf(s, 0.f) + log1pf(expf(-fabsf(s)));
    out[12288 + b * MM + m] = sp + 0.001f;
}

// ------------------------------- launcher --------------------------------
extern "C" void kernel_launch(void* const* d_in, const int* in_sizes, int n_in,
                              void* d_out, int out_size)
{
    const float* x    = (const float*)d_in[0];
    const float* sn   = (const float*)d_in[1];
    const float* node = (const float*)d_in[2];
    const float* conv1_w = (const float*)d_in[3];  const float* conv1_b = (const float*)d_in[4];
    const float* conv2_w = (const float*)d_in[5];  const float* conv2_b = (const float*)d_in[6];
    const float* conv3_w = (const float*)d_in[7];  const float* conv3_b = (const float*)d_in[8];
    const float* conv4_w = (const float*)d_in[9];  const float* conv4_b = (const float*)d_in[10];
    const float* conv5_w = (const float*)d_in[11]; const float* conv5_b = (const float*)d_in[12];
    const float* knnb1_w = (const float*)d_in[13]; const float* knnb1_b = (const float*)d_in[14];
    const float* knnb2_w = (const float*)d_in[15]; const float* knnb2_b = (const float*)d_in[16];
    const float* knnb3_w = (const float*)d_in[17]; const float* knnb3_b = (const float*)d_in[18];
    const float* knna1_w = (const float*)d_in[19]; const float* knna1_b = (const float*)d_in[20];
    const float* knna2_w = (const float*)d_in[21]; const float* knna2_b = (const float*)d_in[22];
    const float* mlp1_w  = (const float*)d_in[23]; const float* mlp1_b  = (const float*)d_in[24];
    const float* mlp2_w  = (const float*)d_in[25]; const float* mlp2_b  = (const float*)d_in[26];
    const float* mlp3_w  = (const float*)d_in[27]; const float* mlp3_b  = (const float*)d_in[28];
    float* out = (float*)d_out;

    float *bufA, *bufB, *X0, *H;
    int *ballidx, *knnidx;
    cudaGetSymbolAddress((void**)&bufA, d_bufA);
    cudaGetSymbolAddress((void**)&bufB, d_bufB);
    cudaGetSymbolAddress((void**)&X0,   d_X0);
    cudaGetSymbolAddress((void**)&H,    d_H);
    cudaGetSymbolAddress((void**)&ballidx, d_ballidx);
    cudaGetSymbolAddress((void**)&knnidx,  d_knnidx);

    // ---- ball branch ----
    ball_query_kernel<<<(BB * MM * 32 + 255) / 256, 256>>>(x, node, ballidx);
    gather_xb_kernel<<<(COLS1 + 255) / 256, 256>>>(x, sn, node, ballidx, X0);

    gemm_bias_relu<<<dim3(COLS1 / GBN, 1), 256>>>(conv1_w, X0,   conv1_b, bufA, 64, 6,   COLS1, 1);
    gemm_bias_relu<<<dim3(COLS1 / GBN, 1), 256>>>(conv2_w, bufA, conv2_b, bufB, 64, 64,  COLS1, 1);
    gemm_bias_relu<<<dim3(COLS1 / GBN, 1), 256>>>(conv3_w, bufB, conv3_b, bufA, 64, 64,  COLS1, 1);
    max64_concat_kernel<<<dim3(COLSN, 64), 64>>>(bufA, bufB);
    gemm_bias_relu<<<dim3(COLS1 / GBN, 2), 256>>>(conv4_w, bufB, conv4_b, bufA, 128, 128, COLS1, 1);
    gemm_bias_relu<<<dim3(COLS1 / GBN, 2), 256>>>(conv5_w, bufA, conv5_b, bufB, 128, 128, COLS1, 1);
    max64_final_kernel<<<dim3(COLSN, 128), 64>>>(bufB, H);   // feat1 -> H rows 0..127

    // ---- knn branch ----
    knn_select_kernel<<<COLSN, 512>>>(node, knnidx);
    gather_knn_kernel<<<(131 * COLS2 + 255) / 256, 256>>>(node, H, knnidx, bufA);
    gemm_bias_relu<<<dim3(COLS2 / GBN, 4), 256>>>(knnb1_w, bufA, knnb1_b, bufB, 256, 131, COLS2, 1);
    gemm_bias_relu<<<dim3(COLS2 / GBN, 4), 256>>>(knnb2_w, bufB, knnb2_b, bufA, 256, 256, COLS2, 1);
    gemm_bias_relu<<<dim3(COLS2 / GBN, 4), 256>>>(knnb3_w, bufA, knnb3_b, bufB, 256, 256, COLS2, 1);
    max9_concat_kernel<<<(256 * COLSN + 255) / 256, 256>>>(bufB, bufA);
    gemm_bias_relu<<<dim3(COLS2 / GBN, 8), 256>>>(knna1_w, bufA, knna1_b, bufB, 512, 512, COLS2, 1);
    gemm_bias_relu<<<dim3(COLS2 / GBN, 8), 256>>>(knna2_w, bufB, knna2_b, bufA, 512, 512, COLS2, 1);
    max9_final_kernel<<<(512 * COLSN + 255) / 256, 256>>>(bufA, H + (size_t)128 * COLSN);

    // ---- mlp head ----
    gemm_bias_relu<<<dim3(COLSN / GBN, 8), 256>>>(mlp1_w, H,    mlp1_b, bufB, 512, 640, COLSN, 1);
    gemm_bias_relu<<<dim3(COLSN / GBN, 4), 256>>>(mlp2_w, bufB, mlp2_b, bufA, 256, 512, COLSN, 1);
    head_kernel<<<(COLSN + 255) / 256, 256>>>(bufA, mlp3_w, mlp3_b, node, out);

    (void)in_sizes; (void)n_in; (void)out_size;
}

// round 4
// speedup vs baseline: 1.5887x; 1.5887x over previous
#include <cuda_runtime.h>
#include <math.h>
#include <stdint.h>

// Problem constants
#define BB 4
#define NN 16384
#define MM 512
#define COLS1 131072   // BB*MM*64  (ball branch columns)
#define COLS2 18432    // BB*MM*9   (knn branch columns)
#define COLSN 2048     // BB*MM

// ---------------- static scratch (no allocations allowed) ----------------
__device__ float d_bufA[128 * 131072];   // 64 MiB ping
__device__ float d_bufB[128 * 131072];   // 64 MiB pong
__device__ float d_X0[6 * 131072];       // gathered ball input (6 x COLS1)
__device__ float d_H[640 * 2048];        // rows 0..127 = feat1, 128..639 = feat2
__device__ float d_tmp1[512 * 2048];     // per-node maxes
__device__ float d_tmp2[512 * 2048];     // Z (per-node precomputed half + bias)
__device__ int   d_ballidx[131072];      // (B*M, 64)
__device__ int   d_knnidx[18432];        // (B*M, 9)

// ---------------- tf32 helpers -------------------------------------------
__device__ __forceinline__ uint32_t f2tf32(float f) {
    uint32_t r;
    asm("cvt.rna.tf32.f32 %0, %1;" : "=r"(r) : "f"(f));
    return r;
}

__device__ __forceinline__ void mma_tf32(float c[4], const uint32_t a[4], const uint32_t b[2]) {
    asm volatile(
        "mma.sync.aligned.m16n8k8.row.col.f32.tf32.tf32.f32 "
        "{%0,%1,%2,%3}, {%4,%5,%6,%7}, {%8,%9}, {%0,%1,%2,%3};"
        : "+f"(c[0]), "+f"(c[1]), "+f"(c[2]), "+f"(c[3])
        : "r"(a[0]), "r"(a[1]), "r"(a[2]), "r"(a[3]), "r"(b[0]), "r"(b[1]));
}

// ---------------- tf32 tensor-core GEMM ----------------------------------
// C[Mrows x Ncols] = act(W[Mrows x lda (use K cols)] @ X[K x Ncols] + bias)
// bias_mode: 0 = bias[row]; 1 = bias[row*COLSN + (col>>6)]; 2 = bias[row*COLSN + col/9]
// Block tile: BM = WR*32 rows x BN = WC*64 cols, BK = 32, WR*WC warps of tile 32x64.
template<int WR, int WC>
__global__ void __launch_bounds__(WR*WC*32, 2)
gemm_tf32(const float* __restrict__ W, int lda,
          const float* __restrict__ X,
          const float* __restrict__ bias, int bias_mode,
          float* __restrict__ C,
          int Mrows, int K, int Ncols, int do_relu)
{
    constexpr int BM = WR * 32;
    constexpr int BN = WC * 64;
    constexpr int NT = WR * WC * 32;
    constexpr int SA = BM + 8;   // stride ≡ 8 (mod 32): conflict-free frag loads
    constexpr int SB = BN + 8;

    __shared__ __align__(16) uint32_t As[32][SA];  // [k][m]
    __shared__ __align__(16) uint32_t Bs[32][SB];  // [k][n]

    const int tid  = threadIdx.x;
    const int lane = tid & 31;
    const int wid  = tid >> 5;
    const int g = lane >> 2;     // groupID 0..7
    const int t = lane & 3;      // threadID-in-group 0..3
    const int wm0 = (wid / WC) * 32;
    const int wn0 = (wid % WC) * 64;
    const int co0  = blockIdx.y * BM;
    const int col0 = blockIdx.x * BN;

    float acc[2][8][4];
#pragma unroll
    for (int mi = 0; mi < 2; mi++)
#pragma unroll
        for (int nj = 0; nj < 8; nj++)
#pragma unroll
            for (int q = 0; q < 4; q++) acc[mi][nj][q] = 0.f;

    // A-tile loader mapping: row = tid % BM, k4 strided
    const int a_row = tid % BM;
    const int a_k4b = tid / BM;
    // B-tile loader mapping: n4 = tid % (BN/4), kk strided
    constexpr int N4 = BN / 4;
    const int b_n4 = tid % N4;
    const int b_kkb = tid / N4;

    for (int k0 = 0; k0 < K; k0 += 32) {
        __syncthreads();
        // load W tile (BM x 32) -> As[k][m], zero-pad beyond K
        {
            const float* wp = W + (size_t)(co0 + a_row) * lda + k0;
#pragma unroll
            for (int k4 = a_k4b; k4 < 8; k4 += NT / BM) {
#pragma unroll
                for (int i = 0; i < 4; i++) {
                    int kk = k4 * 4 + i;
                    uint32_t v = 0;
                    if (k0 + kk < K) v = f2tf32(__ldg(wp + kk));
                    As[kk][a_row] = v;
                }
            }
        }
        // load X tile (32 x BN) -> Bs[k][n] via float4, zero-pad beyond K
        {
#pragma unroll
            for (int kk = b_kkb; kk < 32; kk += NT / N4) {
                int kg = k0 + kk;
                float4 v = make_float4(0.f, 0.f, 0.f, 0.f);
                if (kg < K)
                    v = *reinterpret_cast<const float4*>(&X[(size_t)kg * Ncols + col0 + b_n4 * 4]);
                uint4 u;
                u.x = f2tf32(v.x); u.y = f2tf32(v.y); u.z = f2tf32(v.z); u.w = f2tf32(v.w);
                *reinterpret_cast<uint4*>(&Bs[kk][b_n4 * 4]) = u;
            }
        }
        __syncthreads();

#pragma unroll
        for (int ks = 0; ks < 4; ks++) {
            const int k = ks * 8;
            uint32_t a[2][4], b[8][2];
#pragma unroll
            for (int mi = 0; mi < 2; mi++) {
                int m = wm0 + mi * 16;
                a[mi][0] = As[k + t][m + g];
                a[mi][1] = As[k + t][m + g + 8];
                a[mi][2] = As[k + t + 4][m + g];
                a[mi][3] = As[k + t + 4][m + g + 8];
            }
#pragma unroll
            for (int nj = 0; nj < 8; nj++) {
                int n = wn0 + nj * 8;
                b[nj][0] = Bs[k + t][n + g];
                b[nj][1] = Bs[k + t + 4][n + g];
            }
#pragma unroll
            for (int mi = 0; mi < 2; mi++)
#pragma unroll
                for (int nj = 0; nj < 8; nj++)
                    mma_tf32(acc[mi][nj], a[mi], b[nj]);
        }
    }

    // epilogue: bias (3 modes) + relu, float2 stores
#pragma unroll
    for (int mi = 0; mi < 2; mi++) {
        const int r0 = co0 + wm0 + mi * 16 + g;
        const int r1 = r0 + 8;
        float brs0 = 0.f, brs1 = 0.f;
        if (bias_mode == 0) { brs0 = bias[r0]; brs1 = bias[r1]; }
#pragma unroll
        for (int nj = 0; nj < 8; nj++) {
            const int cb = col0 + wn0 + nj * 8 + 2 * t;
            float b00, b01, b10, b11;
            if (bias_mode == 0) {
                b00 = b01 = brs0; b10 = b11 = brs1;
            } else if (bias_mode == 1) {
                int nid = cb >> 6;   // cb even -> cb and cb+1 share node
                b00 = b01 = bias[(size_t)r0 * COLSN + nid];
                b10 = b11 = bias[(size_t)r1 * COLSN + nid];
            } else {
                int n0 = cb / 9, n1 = (cb + 1) / 9;
                b00 = bias[(size_t)r0 * COLSN + n0];
                b01 = bias[(size_t)r0 * COLSN + n1];
                b10 = bias[(size_t)r1 * COLSN + n0];
                b11 = bias[(size_t)r1 * COLSN + n1];
            }
            float v0 = acc[mi][nj][0] + b00;
            float v1 = acc[mi][nj][1] + b01;
            float v2 = acc[mi][nj][2] + b10;
            float v3 = acc[mi][nj][3] + b11;
            if (do_relu) {
                v0 = fmaxf(v0, 0.f); v1 = fmaxf(v1, 0.f);
                v2 = fmaxf(v2, 0.f); v3 = fmaxf(v3, 0.f);
            }
            *reinterpret_cast<float2*>(&C[(size_t)r0 * Ncols + cb]) = make_float2(v0, v1);
            *reinterpret_cast<float2*>(&C[(size_t)r1 * Ncols + cb]) = make_float2(v2, v3);
        }
    }
}

// ---------------- ball query: first 64 in-ball indices in index order -----
__global__ void ball_query_kernel(const float* __restrict__ x,
                                  const float* __restrict__ node,
                                  int* __restrict__ idxout)
{
    int w = (blockIdx.x * blockDim.x + threadIdx.x) >> 5;
    int lane = threadIdx.x & 31;
    if (w >= BB * MM) return;
    int b = w / MM, m = w % MM;
    float nx = node[(b * 3 + 0) * MM + m];
    float ny = node[(b * 3 + 1) * MM + m];
    float nz = node[(b * 3 + 2) * MM + m];
    const float* xb = x + (size_t)b * 3 * NN;
    int base = w * 64;
    int total = 0;
    int firstJ = -1;
    for (int j0 = 0; j0 < NN; j0 += 32) {
        int j = j0 + lane;
        float dx = xb[j] - nx;
        float dy = xb[NN + j] - ny;
        float dz = xb[2 * NN + j] - nz;
        float d = dx * dx + dy * dy + dz * dz;
        bool hit = d < 4.0f;
        unsigned mask = __ballot_sync(0xffffffffu, hit);
        if (firstJ < 0 && mask) firstJ = j0 + __ffs(mask) - 1;
        int pos = total + __popc(mask & ((1u << lane) - 1u));
        if (hit && pos < 64) idxout[base + pos] = j;
        total += __popc(mask);
        if (total >= 64) break;
    }
    if (total < 64) {
        int f = (firstJ < 0) ? 0 : firstJ;
        for (int p = total + lane; p < 64; p += 32) idxout[base + p] = f;
    }
}

// ---------------- gather ball neighborhood: X0 (6 x COLS1) ---------------
__global__ void gather_xb_kernel(const float* __restrict__ x,
                                 const float* __restrict__ sn,
                                 const float* __restrict__ node,
                                 const int* __restrict__ idx,
                                 float* __restrict__ X0)
{
    int col = blockIdx.x * blockDim.x + threadIdx.x;
    if (col >= COLS1) return;
    int nodeid = col >> 6;          // b*MM + m
    int b = nodeid / MM, m = nodeid % MM;
    int j = idx[col];
    const float* xb = x  + (size_t)b * 3 * NN;
    const float* sb = sn + (size_t)b * 3 * NN;
    X0[(size_t)0 * COLS1 + col] = xb[j]          - node[(b * 3 + 0) * MM + m];
    X0[(size_t)1 * COLS1 + col] = xb[NN + j]     - node[(b * 3 + 1) * MM + m];
    X0[(size_t)2 * COLS1 + col] = xb[2 * NN + j] - node[(b * 3 + 2) * MM + m];
    X0[(size_t)3 * COLS1 + col] = sb[j];
    X0[(size_t)4 * COLS1 + col] = sb[NN + j];
    X0[(size_t)5 * COLS1 + col] = sb[2 * NN + j];
}

// -------- per-node max over k=64: in (rows x COLS1) -> out (rows x COLSN) --
// grid (COLSN, rows), block 64
__global__ void max64_rows_kernel(const float* __restrict__ f,
                                  float* __restrict__ Hrows)
{
    int nodeid = blockIdx.x;
    int row = blockIdx.y;
    int k = threadIdx.x;            // 0..63
    float v = f[(size_t)row * COLS1 + nodeid * 64 + k];
#pragma unroll
    for (int o = 16; o; o >>= 1) v = fmaxf(v, __shfl_xor_sync(0xffffffffu, v, o));
    __shared__ float s[2];
    if ((k & 31) == 0) s[k >> 5] = v;
    __syncthreads();
    if (k == 0) Hrows[(size_t)row * COLSN + nodeid] = fmaxf(s[0], s[1]);
}

// -------- per-node max over k=9: in (rows x COLS2) -> out (rows x COLSN) ---
__global__ void max9_rows_kernel(const float* __restrict__ g,
                                 float* __restrict__ Hrows, int rows)
{
    int e = blockIdx.x * blockDim.x + threadIdx.x;
    if (e >= rows * COLSN) return;
    int row = e / COLSN, nid = e % COLSN;
    size_t base = (size_t)row * COLS2 + nid * 9;
    float mx = -3.4e38f;
#pragma unroll
    for (int k = 0; k < 9; k++) mx = fmaxf(mx, g[base + k]);
    Hrows[(size_t)row * COLSN + nid] = mx;
}

// ---------------- 9-NN among nodes (tie-break: smaller index) -------------
__global__ void knn_select_kernel(const float* __restrict__ node,
                                  int* __restrict__ knnidx)
{
    int nid = blockIdx.x;           // 0..2047
    int b = nid >> 9, m = nid & 511;
    int j = threadIdx.x;            // 0..511
    __shared__ float rd[16];
    __shared__ int   ri[16];
    __shared__ int   sbest;
    float nx = node[(b * 3 + 0) * MM + m];
    float ny = node[(b * 3 + 1) * MM + m];
    float nz = node[(b * 3 + 2) * MM + m];
    float dx = node[(b * 3 + 0) * MM + j] - nx;
    float dy = node[(b * 3 + 1) * MM + j] - ny;
    float dz = node[(b * 3 + 2) * MM + j] - nz;
    float d = dx * dx + dy * dy + dz * dz;
    for (int t = 0; t < 9; t++) {
        float bd = d; int bi = j;
#pragma unroll
        for (int o = 16; o; o >>= 1) {
            float od = __shfl_xor_sync(0xffffffffu, bd, o);
            int   oi = __shfl_xor_sync(0xffffffffu, bi, o);
            if (od < bd || (od == bd && oi < bi)) { bd = od; bi = oi; }
        }
        if ((j & 31) == 0) { rd[j >> 5] = bd; ri[j >> 5] = bi; }
        __syncthreads();
        if (j == 0) {
            float best = rd[0]; int besti = ri[0];
            for (int w = 1; w < 16; w++)
                if (rd[w] < best || (rd[w] == best && ri[w] < besti)) { best = rd[w]; besti = ri[w]; }
            knnidx[nid * 9 + t] = besti;
            sbest = besti;
        }
        __syncthreads();
        if (j == sbest) d = 3.4e38f;
    }
}

// -------- gather knn inputs: g0 (131 x COLS2): [coords-diff(3); feat1(128)]
__global__ void gather_knn_kernel(const float* __restrict__ node,
                                  const float* __restrict__ H,   // feat1 rows 0..127
                                  const int* __restrict__ knnidx,
                                  float* __restrict__ g0)
{
    int e = blockIdx.x * blockDim.x + threadIdx.x;
    if (e >= 131 * COLS2) return;
    int row = e / COLS2, col = e % COLS2;
    int nid = col / 9;
    int b = nid >> 9, m = nid & 511;
    int j = knnidx[col];
    float v;
    if (row < 3)
        v = node[(b * 3 + row) * MM + j] - node[(b * 3 + row) * MM + m];
    else
        v = H[(size_t)(row - 3) * COLSN + b * MM + j];
    g0[e] = v;
}

// -------- head: mlp3 (4x256) + softplus + assemble final output ----------
__global__ void head_kernel(const float* __restrict__ m2,    // 256 x 2048
                            const float* __restrict__ w3,    // 4 x 256
                            const float* __restrict__ b3,    // 4
                            const float* __restrict__ node,
                            float* __restrict__ out)
{
    int col = blockIdx.x * blockDim.x + threadIdx.x;
    if (col >= COLSN) return;
    int b = col >> 9, m = col & 511;
    float acc0 = b3[0], acc1 = b3[1], acc2 = b3[2], acc3 = b3[3];
    for (int ci = 0; ci < 256; ci++) {
        float xv = m2[(size_t)ci * COLSN + col];
        acc0 += w3[0 * 256 + ci] * xv;
        acc1 += w3[1 * 256 + ci] * xv;
        acc2 += w3[2 * 256 + ci] * xv;
        acc3 += w3[3 * 256 + ci] * xv;
    }
    float kv[3] = {acc0, acc1, acc2};
#pragma unroll
    for (int c = 0; c < 3; c++) {
        float nv = node[(b * 3 + c) * MM + m];
        out[(b * 3 + c) * MM + m] = nv;                   // node passthrough
        out[6144 + (b * 3 + c) * MM + m] = kv[c] + nv;    // keypoints
    }
    float s = acc3;
    float sp = fmaxf(s, 0.f) + log1pf(expf(-fabsf(s)));
    out[12288 + b * MM + m] = sp + 0.001f;
}

// ------------------------------- launcher --------------------------------
extern "C" void kernel_launch(void* const* d_in, const int* in_sizes, int n_in,
                              void* d_out, int out_size)
{
    const float* x    = (const float*)d_in[0];
    const float* sn   = (const float*)d_in[1];
    const float* node = (const float*)d_in[2];
    const float* conv1_w = (const float*)d_in[3];  const float* conv1_b = (const float*)d_in[4];
    const float* conv2_w = (const float*)d_in[5];  const float* conv2_b = (const float*)d_in[6];
    const float* conv3_w = (const float*)d_in[7];  const float* conv3_b = (const float*)d_in[8];
    const float* conv4_w = (const float*)d_in[9];  const float* conv4_b = (const float*)d_in[10];
    const float* conv5_w = (const float*)d_in[11]; const float* conv5_b = (const float*)d_in[12];
    const float* knnb1_w = (const float*)d_in[13]; const float* knnb1_b = (const float*)d_in[14];
    const float* knnb2_w = (const float*)d_in[15]; const float* knnb2_b = (const float*)d_in[16];
    const float* knnb3_w = (const float*)d_in[17]; const float* knnb3_b = (const float*)d_in[18];
    const float* knna1_w = (const float*)d_in[19]; const float* knna1_b = (const float*)d_in[20];
    const float* knna2_w = (const float*)d_in[21]; const float* knna2_b = (const float*)d_in[22];
    const float* mlp1_w  = (const float*)d_in[23]; const float* mlp1_b  = (const float*)d_in[24];
    const float* mlp2_w  = (const float*)d_in[25]; const float* mlp2_b  = (const float*)d_in[26];
    const float* mlp3_w  = (const float*)d_in[27]; const float* mlp3_b  = (const float*)d_in[28];
    float* out = (float*)d_out;

    float *bufA, *bufB, *X0, *H, *tmp1, *tmp2;
    int *ballidx, *knnidx;
    cudaGetSymbolAddress((void**)&bufA, d_bufA);
    cudaGetSymbolAddress((void**)&bufB, d_bufB);
    cudaGetSymbolAddress((void**)&X0,   d_X0);
    cudaGetSymbolAddress((void**)&H,    d_H);
    cudaGetSymbolAddress((void**)&tmp1, d_tmp1);
    cudaGetSymbolAddress((void**)&tmp2, d_tmp2);
    cudaGetSymbolAddress((void**)&ballidx, d_ballidx);
    cudaGetSymbolAddress((void**)&knnidx,  d_knnidx);

    // ---- ball branch ----
    ball_query_kernel<<<(BB * MM * 32 + 255) / 256, 256>>>(x, node, ballidx);
    gather_xb_kernel<<<(COLS1 + 255) / 256, 256>>>(x, sn, node, ballidx, X0);

    // conv1..3: M=64 -> config <2,4> (BM=64, BN=256)
    gemm_tf32<2, 4><<<dim3(COLS1 / 256, 1), 256>>>(conv1_w, 6,  X0,   conv1_b, 0, bufA, 64, 6,  COLS1, 1);
    gemm_tf32<2, 4><<<dim3(COLS1 / 256, 1), 256>>>(conv2_w, 64, bufA, conv2_b, 0, bufB, 64, 64, COLS1, 1);
    gemm_tf32<2, 4><<<dim3(COLS1 / 256, 1), 256>>>(conv3_w, 64, bufB, conv3_b, 0, bufA, 64, 64, COLS1, 1);

    // fmax (64 x 2048), then Z4 = conv4_w[:,64:128] @ fmax + b4 (no relu)
    max64_rows_kernel<<<dim3(COLSN, 64), 64>>>(bufA, tmp1);
    gemm_tf32<4, 2><<<dim3(COLSN / 128, 1), 256>>>(conv4_w + 64, 128, tmp1, conv4_b, 0, tmp2, 128, 64, COLSN, 0);
    // conv4: relu(conv4_w[:,0:64] @ f3 + Z4[row][col>>6])
    gemm_tf32<4, 2><<<dim3(COLS1 / 128, 1), 256>>>(conv4_w, 128, bufA, tmp2, 1, bufB, 128, 64, COLS1, 1);
    gemm_tf32<4, 2><<<dim3(COLS1 / 128, 1), 256>>>(conv5_w, 128, bufB, conv5_b, 0, bufA, 128, 128, COLS1, 1);
    max64_rows_kernel<<<dim3(COLSN, 128), 64>>>(bufA, H);   // feat1 -> H rows 0..127

    // ---- knn branch ----
    knn_select_kernel<<<COLSN, 512>>>(node, knnidx);
    gather_knn_kernel<<<(131 * COLS2 + 255) / 256, 256>>>(node, H, knnidx, bufA);
    gemm_tf32<4, 2><<<dim3(COLS2 / 128, 2), 256>>>(knnb1_w, 131, bufA, knnb1_b, 0, bufB, 256, 131, COLS2, 1);
    gemm_tf32<4, 2><<<dim3(COLS2 / 128, 2), 256>>>(knnb2_w, 256, bufB, knnb2_b, 0, bufA, 256, 256, COLS2, 1);
    gemm_tf32<4, 2><<<dim3(COLS2 / 128, 2), 256>>>(knnb3_w, 256, bufA, knnb3_b, 0, bufB, 256, 256, COLS2, 1);

    // gmax (256 x 2048), then Zk = knna1_w[:,256:512] @ gmax + b (no relu)
    max9_rows_kernel<<<(256 * COLSN + 255) / 256, 256>>>(bufB, tmp1, 256);
    gemm_tf32<4, 2><<<dim3(COLSN / 128, 4), 256>>>(knna1_w + 256, 512, tmp1, knna1_b, 0, tmp2, 512, 256, COLSN, 0);
    // knna1: relu(knna1_w[:,0:256] @ g3 + Zk[row][col/9])
    gemm_tf32<4, 2><<<dim3(COLS2 / 128, 4), 256>>>(knna1_w, 512, bufB, tmp2, 2, bufA, 512, 256, COLS2, 1);
    gemm_tf32<4, 2><<<dim3(COLS2 / 128, 4), 256>>>(knna2_w, 512, bufA, knna2_b, 0, bufB, 512, 512, COLS2, 1);
    max9_rows_kernel<<<(512 * COLSN + 255) / 256, 256>>>(bufB, H + (size_t)128 * COLSN, 512);

    // ---- mlp head ----
    gemm_tf32<4, 2><<<dim3(COLSN / 128, 4), 256>>>(mlp1_w, 640, H,    mlp1_b, 0, bufA, 512, 640, COLSN, 1);
    gemm_tf32<4, 2><<<dim3(COLSN / 128, 2), 256>>>(mlp2_w, 512, bufA, mlp2_b, 0, bufB, 256, 512, COLSN, 1);
    head_kernel<<<(COLSN + 255) / 256, 256>>>(bufB, mlp3_w, mlp3_b, node, out);

    (void)in_sizes; (void)n_in; (void)out_size;
}